// round 5
// baseline (speedup 1.0000x reference)
#include <cuda_runtime.h>
#include <cuda_bf16.h>
#include <cstdint>

// Clipped Poisson-binomial severity kernel, round 4.
// R3's independent-block structure (which sustains DRAM ~79%) + R2's packed
// f32x2 recurrence (2 rows/thread, ~2.9 fma-slots/row instead of 10) to test
// whether the fma stream is what keeps DRAM off its ceiling.

#define NT 128               // threads per block
#define ROWS 256             // rows per block (2 per thread)
#define SSTRIDE 36           // padded floats per smem row -> conflict-free LDS.128
#define IN_FLOATS (ROWS * SSTRIDE)           // 9216 floats per input tile
#define SMEM_BYTES (3 * IN_FLOATS * 4)       // 110,592 B -> 2 blocks/SM

typedef unsigned long long u64;

__device__ __forceinline__ u64 pk2(float a, float b) {
    u64 r; asm("mov.b64 %0, {%1, %2};" : "=l"(r) : "f"(a), "f"(b)); return r;
}
__device__ __forceinline__ void upk2(u64 v, float& a, float& b) {
    asm("mov.b64 {%0, %1}, %2;" : "=f"(a), "=f"(b) : "l"(v));
}
__device__ __forceinline__ u64 fma2(u64 a, u64 b, u64 c) {
    u64 d; asm("fma.rn.f32x2 %0, %1, %2, %3;" : "=l"(d) : "l"(a), "l"(b), "l"(c)); return d;
}

__global__ void __launch_bounds__(NT)
hemorrhage_sev_kernel(const float* __restrict__ x1,
                      const float* __restrict__ x2,
                      const float* __restrict__ x3,
                      float* __restrict__ out,
                      int nrows)
{
    extern __shared__ float s[];

    const int t = threadIdx.x;
    const long long rowBase = (long long)blockIdx.x * ROWS;
    const int rowsHere = (int)min((long long)ROWS, (long long)nrows - rowBase);

    const float* srcs[3] = { x1 + rowBase * 32, x2 + rowBase * 32, x3 + rowBase * 32 };

    // ---- Stage all three inputs, one commit group per input ----
    #pragma unroll
    for (int in = 0; in < 3; ++in) {
        const float4* gp = (const float4*)srcs[in];
        float* bb = s + in * IN_FLOATS;
        #pragma unroll
        for (int k = 0; k < 16; ++k) {           // 16 * 128 = 2048 float4 per input
            int i = k * NT + t;
            int row  = i >> 3;                   // 8 float4 per row
            int col4 = i & 7;
            float* dst = bb + row * SSTRIDE + col4 * 4;
            unsigned saddr = (unsigned)__cvta_generic_to_shared(dst);
            int srcsz = (row < rowsHere) ? 16 : 0;   // zero-fill OOB rows
            asm volatile("cp.async.cg.shared.global [%0], [%1], 16, %2;\n"
                         :: "r"(saddr), "l"(gp + i), "r"(srcsz));
        }
        asm volatile("cp.async.commit_group;\n");
    }

    // ---- Packed recurrence: thread t owns rows t (lo lane) and t+128 (hi) ----
    u64 c0 = pk2(1.f, 1.f), c1 = 0, c2 = 0, c3 = 0, c4 = 0, c5 = 0;

    #pragma unroll
    for (int in = 0; in < 3; ++in) {
        if (in == 0)      asm volatile("cp.async.wait_group 2;\n");
        else if (in == 1) asm volatile("cp.async.wait_group 1;\n");
        else              asm volatile("cp.async.wait_group 0;\n");
        __syncthreads();

        const float* rA = s + in * IN_FLOATS + t * SSTRIDE;
        const float* rB = rA + 128 * SSTRIDE;
        #pragma unroll
        for (int j4 = 0; j4 < 8; ++j4) {
            float4 va = *(const float4*)(rA + j4 * 4);
            float4 vb = *(const float4*)(rB + j4 * 4);
            float pa[4] = { va.x, va.y, va.z, va.w };
            float pb[4] = { vb.x, vb.y, vb.z, vb.w };
            #pragma unroll
            for (int u = 0; u < 4; ++u) {
                u64 p  = pk2(pa[u], pb[u]);
                u64 np = p ^ 0x8000000080000000ull;   // -p (alu pipe, off fma)
                c5 = fma2(c4, p, c5);                 // absorbing top (old c4)
                c4 = fma2(c3, p, fma2(c4, np, c4));   // c4*(1-p) + c3*p
                c3 = fma2(c2, p, fma2(c3, np, c3));
                c2 = fma2(c1, p, fma2(c2, np, c2));
                c1 = fma2(c0, p, fma2(c1, np, c1));
                c0 = fma2(c0, np, c0);                // c0 *= (1-p)
            }
        }
    }
    __syncthreads();   // everyone done reading input smem; reuse it for output

    // ---- Stage outputs in smem (stride-5 -> conflict-free), coalesced store ----
    float a0,b0,a1,b1,a2,b2,a3,b3,a4,b4,a5,b5;
    upk2(c0,a0,b0); upk2(c1,a1,b1); upk2(c2,a2,b2);
    upk2(c3,a3,b3); upk2(c4,a4,b4); upk2(c5,a5,b5);

    float* so = s;                        // 256*5 = 1280 floats, fits easily
    so[t * 5 + 0] = a0;
    so[t * 5 + 1] = a1 + a2;
    so[t * 5 + 2] = a3 + a4;
    so[t * 5 + 3] = a5;
    so[t * 5 + 4] = 0.f;
    so[(t + 128) * 5 + 0] = b0;
    so[(t + 128) * 5 + 1] = b1 + b2;
    so[(t + 128) * 5 + 2] = b3 + b4;
    so[(t + 128) * 5 + 3] = b5;
    so[(t + 128) * 5 + 4] = 0.f;
    __syncthreads();

    float* og = out + rowBase * 5;
    const int nOut = rowsHere * 5;        // <= 1280
    #pragma unroll
    for (int k = 0; k < 10; ++k) {
        int idx = k * NT + t;
        if (idx < nOut) og[idx] = so[idx];
    }
}

extern "C" void kernel_launch(void* const* d_in, const int* in_sizes, int n_in,
                              void* d_out, int out_size)
{
    const float* x1 = (const float*)d_in[0];
    const float* x2 = (const float*)d_in[1];
    const float* x3 = (const float*)d_in[2];
    float* out = (float*)d_out;

    const int nrows = in_sizes[0] / 32;
    const int nblocks = (nrows + ROWS - 1) / ROWS;

    static bool attrSet = false;
    if (!attrSet) {
        cudaFuncSetAttribute(hemorrhage_sev_kernel,
                             cudaFuncAttributeMaxDynamicSharedMemorySize, SMEM_BYTES);
        attrSet = true;
    }

    hemorrhage_sev_kernel<<<nblocks, NT, SMEM_BYTES>>>(x1, x2, x3, out, nrows);
}

// round 6
// speedup vs baseline: 1.0449x; 1.0449x over previous
#include <cuda_runtime.h>
#include <cuda_bf16.h>
#include <cstdint>

// Clipped Poisson-binomial severity kernel, round 5.
// R3 structure (best so far: independent 128-thread blocks, per-input cp.async
// commit groups, progressive waits, scalar recurrence) with two changes aimed
// purely at achieved-DRAM-bandwidth:
//   * output staging reuses input smem  -> 55.3 KB/block -> 4 blocks/SM
//   * output drained with float4 evict-first stores (STG.E.128.CS)

#define NT 128               // threads per block
#define ROWS 128             // rows per block (1 per thread)
#define SSTRIDE 36           // padded floats per smem row -> conflict-free LDS.128
#define IN_FLOATS (ROWS * SSTRIDE)   // 4608 floats per input tile

__global__ __launch_bounds__(NT, 4)
void hemorrhage_sev_kernel(const float* __restrict__ x1,
                           const float* __restrict__ x2,
                           const float* __restrict__ x3,
                           float* __restrict__ out,
                           int nrows)
{
    __shared__ float s[3 * IN_FLOATS];          // 55,296 B; reused for output

    const int t = threadIdx.x;
    const long long rowBase = (long long)blockIdx.x * ROWS;
    const int rowsHere = (int)min((long long)ROWS, (long long)nrows - rowBase);

    const float* srcs[3] = { x1 + rowBase * 32, x2 + rowBase * 32, x3 + rowBase * 32 };

    // ---- Stage all three inputs, one commit group per input ----
    #pragma unroll
    for (int in = 0; in < 3; ++in) {
        const float4* gp = (const float4*)srcs[in];
        float* bb = s + in * IN_FLOATS;
        #pragma unroll
        for (int k = 0; k < 8; ++k) {            // 8 * 128 = 1024 float4 per input
            int i = k * NT + t;
            int row  = i >> 3;                   // 8 float4 per row
            int col4 = i & 7;
            float* dst = bb + row * SSTRIDE + col4 * 4;
            unsigned saddr = (unsigned)__cvta_generic_to_shared(dst);
            int srcsz = (row < rowsHere) ? 16 : 0;   // zero-fill OOB rows
            asm volatile("cp.async.cg.shared.global [%0], [%1], 16, %2;\n"
                         :: "r"(saddr), "l"(gp + i), "r"(srcsz));
        }
        asm volatile("cp.async.commit_group;\n");
    }

    // ---- Recurrence, consuming inputs as their groups land ----
    float c0 = 1.f, c1 = 0.f, c2 = 0.f, c3 = 0.f, c4 = 0.f, c5 = 0.f;

    #pragma unroll
    for (int in = 0; in < 3; ++in) {
        if (in == 0)      asm volatile("cp.async.wait_group 2;\n");
        else if (in == 1) asm volatile("cp.async.wait_group 1;\n");
        else              asm volatile("cp.async.wait_group 0;\n");
        __syncthreads();

        const float* rowp = s + in * IN_FLOATS + t * SSTRIDE;
        #pragma unroll
        for (int j4 = 0; j4 < 8; ++j4) {
            float4 v = *(const float4*)(rowp + j4 * 4);
            float pv[4] = { v.x, v.y, v.z, v.w };
            #pragma unroll
            for (int u = 0; u < 4; ++u) {
                float p = pv[u];
                c5 = fmaf(c4, p, c5);            // absorbing top bucket (old c4)
                c4 = fmaf(c3 - c4, p, c4);
                c3 = fmaf(c2 - c3, p, c3);
                c2 = fmaf(c1 - c2, p, c2);
                c1 = fmaf(c0 - c1, p, c1);
                c0 = fmaf(-c0, p, c0);           // c0 *= (1-p)
            }
        }
    }
    __syncthreads();   // input tiles fully consumed; reuse smem for output

    // ---- Stage output (stride-5 STS, gcd(5,32)=1 -> conflict-free) ----
    float* so = s;     // 640 floats needed
    so[t * 5 + 0] = c0;
    so[t * 5 + 1] = c1 + c2;
    so[t * 5 + 2] = c3 + c4;
    so[t * 5 + 3] = c5;
    so[t * 5 + 4] = 0.f;
    __syncthreads();

    // ---- Drain: vector evict-first stores (full block), scalar for tail ----
    float* og = out + rowBase * 5;
    if (rowsHere == ROWS) {
        // 640 floats = 160 float4; base is 16B-aligned (rowBase*5*4 = 2560*bid)
        float4* og4 = (float4*)og;
        const float4* so4 = (const float4*)so;
        #pragma unroll
        for (int k = 0; k < 2; ++k) {
            int idx = k * NT + t;
            if (idx < (ROWS * 5) / 4) __stcs(og4 + idx, so4[idx]);
        }
    } else {
        const int nOut = rowsHere * 5;
        #pragma unroll
        for (int k = 0; k < 5; ++k) {
            int idx = k * NT + t;
            if (idx < nOut) og[idx] = so[idx];
        }
    }
}

extern "C" void kernel_launch(void* const* d_in, const int* in_sizes, int n_in,
                              void* d_out, int out_size)
{
    const float* x1 = (const float*)d_in[0];
    const float* x2 = (const float*)d_in[1];
    const float* x3 = (const float*)d_in[2];
    float* out = (float*)d_out;

    const int nrows = in_sizes[0] / 32;
    const int nblocks = (nrows + ROWS - 1) / ROWS;

    hemorrhage_sev_kernel<<<nblocks, NT>>>(x1, x2, x3, out, nrows);
}

// round 7
// speedup vs baseline: 1.0594x; 1.0139x over previous
#include <cuda_runtime.h>
#include <cuda_bf16.h>
#include <cstdint>

// Clipped Poisson-binomial severity kernel, round 6.
// Same proven structure (independent 128-thread blocks, progressive per-input
// consumption, scalar recurrence, staged vector output), but staging now uses
// cp.async.bulk (3 bulk copies + mbarriers per block instead of 3072 LDGSTS),
// and smem is unpadded raw rows with rotation-ordered conflict-free LDS.128.

#define NT 128               // threads per block
#define ROWS 128             // rows per block (1 per thread)
#define IN_BYTES (ROWS * 32 * 4)     // 16,384 B per input tile
#define IN_FLOATS (ROWS * 32)

__global__ __launch_bounds__(NT, 4)
void hemorrhage_sev_kernel(const float* __restrict__ x1,
                           const float* __restrict__ x2,
                           const float* __restrict__ x3,
                           float* __restrict__ out,
                           int nrows)
{
    __shared__ float s[3 * IN_FLOATS];              // 49,152 B, raw 128B rows
    __shared__ __align__(8) unsigned long long mbar[3];

    const int t = threadIdx.x;
    const long long rowBase = (long long)blockIdx.x * ROWS;
    const int rowsHere = (int)min((long long)ROWS, (long long)nrows - rowBase);

    const float* srcs[3] = { x1 + rowBase * 32, x2 + rowBase * 32, x3 + rowBase * 32 };

    // ---- mbarrier init (count=1 each) ----
    if (t == 0) {
        #pragma unroll
        for (int in = 0; in < 3; ++in) {
            unsigned mb = (unsigned)__cvta_generic_to_shared(&mbar[in]);
            asm volatile("mbarrier.init.shared.b64 [%0], 1;" :: "r"(mb));
        }
    }
    __syncthreads();

    // ---- issue 3 bulk copies, one completion barrier per input ----
    if (t == 0) {
        const unsigned bytes = (unsigned)(rowsHere * 128);
        #pragma unroll
        for (int in = 0; in < 3; ++in) {
            unsigned mb  = (unsigned)__cvta_generic_to_shared(&mbar[in]);
            unsigned dst = (unsigned)__cvta_generic_to_shared(s + in * IN_FLOATS);
            asm volatile("mbarrier.arrive.expect_tx.shared.b64 _, [%0], %1;"
                         :: "r"(mb), "r"(bytes));
            asm volatile(
                "cp.async.bulk.shared::cta.global.mbarrier::complete_tx::bytes "
                "[%0], [%1], %2, [%3];"
                :: "r"(dst), "l"(srcs[in]), "r"(bytes), "r"(mb) : "memory");
        }
    }
    __syncthreads();   // mb addresses + arrive visible; all threads now wait per input

    // ---- recurrence, consuming each input as its bulk copy lands ----
    float c0 = 1.f, c1 = 0.f, c2 = 0.f, c3 = 0.f, c4 = 0.f, c5 = 0.f;

    #pragma unroll
    for (int in = 0; in < 3; ++in) {
        {   // acquire-wait on this input's barrier, phase parity 0
            unsigned mb = (unsigned)__cvta_generic_to_shared(&mbar[in]);
            unsigned done;
            asm volatile(
                "{\n\t.reg .pred p;\n\t"
                "mbarrier.try_wait.parity.acquire.cta.shared::cta.b64 p, [%1], 0;\n\t"
                "selp.b32 %0, 1, 0, p;\n\t}"
                : "=r"(done) : "r"(mb) : "memory");
            while (!done) {
                asm volatile(
                    "{\n\t.reg .pred p;\n\t"
                    "mbarrier.try_wait.parity.acquire.cta.shared::cta.b64 p, [%1], 0;\n\t"
                    "selp.b32 %0, 1, 0, p;\n\t}"
                    : "=r"(done) : "r"(mb) : "memory");
            }
        }

        // rotation-ordered reads: thread t consumes float4 index (t+i)&7.
        // Within each 8-lane LDS phase the indices are distinct -> 32 disjoint
        // banks -> conflict-free without padding. Order change is benign
        // (distribution is permutation-invariant in the probabilities).
        const float4* rowp = (const float4*)(s + in * IN_FLOATS + t * 32);
        const int rot = t & 7;
        #pragma unroll
        for (int i = 0; i < 8; ++i) {
            float4 v = rowp[(rot + i) & 7];
            float pv[4] = { v.x, v.y, v.z, v.w };
            #pragma unroll
            for (int u = 0; u < 4; ++u) {
                float p = pv[u];
                c5 = fmaf(c4, p, c5);            // absorbing top bucket (old c4)
                c4 = fmaf(c3 - c4, p, c4);
                c3 = fmaf(c2 - c3, p, c3);
                c2 = fmaf(c1 - c2, p, c2);
                c1 = fmaf(c0 - c1, p, c1);
                c0 = fmaf(-c0, p, c0);           // c0 *= (1-p)
            }
        }
    }
    __syncthreads();   // input tiles fully consumed; reuse smem for output

    // ---- stage output (stride-5 STS, gcd(5,32)=1 -> conflict-free) ----
    float* so = s;     // 640 floats
    so[t * 5 + 0] = c0;
    so[t * 5 + 1] = c1 + c2;
    so[t * 5 + 2] = c3 + c4;
    so[t * 5 + 3] = c5;
    so[t * 5 + 4] = 0.f;
    __syncthreads();

    // ---- drain: vector evict-first stores; scalar fallback on tail ----
    float* og = out + rowBase * 5;
    if (rowsHere == ROWS) {
        float4* og4 = (float4*)og;               // base 16B-aligned (2560B/block)
        const float4* so4 = (const float4*)so;
        #pragma unroll
        for (int k = 0; k < 2; ++k) {
            int idx = k * NT + t;
            if (idx < (ROWS * 5) / 4) __stcs(og4 + idx, so4[idx]);
        }
    } else {
        const int nOut = rowsHere * 5;
        #pragma unroll
        for (int k = 0; k < 5; ++k) {
            int idx = k * NT + t;
            if (idx < nOut) og[idx] = so[idx];
        }
    }
}

extern "C" void kernel_launch(void* const* d_in, const int* in_sizes, int n_in,
                              void* d_out, int out_size)
{
    const float* x1 = (const float*)d_in[0];
    const float* x2 = (const float*)d_in[1];
    const float* x3 = (const float*)d_in[2];
    float* out = (float*)d_out;

    const int nrows = in_sizes[0] / 32;
    const int nblocks = (nrows + ROWS - 1) / ROWS;

    hemorrhage_sev_kernel<<<nblocks, NT>>>(x1, x2, x3, out, nrows);
}